// round 1
// baseline (speedup 1.0000x reference)
#include <cuda_runtime.h>
#include <cstdint>

// Problem constants
#define L_SEQ 1024
#define BATCH_BS 8
#define EMB 512
#define NH 8
#define DH 64
#define O3 1536          // 3*NH*DH
#define MROWS 8192       // L_SEQ * BATCH_BS
#define NB 64            // BATCH_BS * NH

// Scratch (device globals — no allocation allowed in kernel_launch)
__device__ float g_C[(size_t)MROWS * O3];              // qkv projection output (+bias), 50 MB
__device__ float g_E[(size_t)NB * L_SEQ * L_SEQ];      // exp(scores), 268 MB
__device__ float g_Z[NB * L_SEQ];                      // row sums -> reciprocals
__device__ float g_W[NB * L_SEQ];                      // attn_weights (column sums)

// ---------------------------------------------------------------------------
// K0: zero Z (needed every graph replay since K2 accumulates with atomics)
// ---------------------------------------------------------------------------
__global__ void k_zzero() {
    g_Z[blockIdx.x * 1024 + threadIdx.x] = 0.0f;
}

// ---------------------------------------------------------------------------
// K1: C[8192,1536] = emb[8192,512] @ W_qkv[1536,512]^T + bias   (NT sgemm)
// 128x128 tile, BK=8, 256 threads, 8x8 per-thread register tile.
// ---------------------------------------------------------------------------
__global__ void __launch_bounds__(256) k1_qkv_gemm(
    const float* __restrict__ A, const float* __restrict__ Wt,
    const float* __restrict__ bias)
{
    __shared__ float As[8][128];
    __shared__ float Bs[8][128];
    const int tid = threadIdx.x;
    const int m0 = blockIdx.y * 128;
    const int n0 = blockIdx.x * 128;
    const int lr = tid >> 1;            // 0..127 (row within tile for loading)
    const int lc = (tid & 1) << 2;      // 0 or 4 (k offset for loading)
    const int tx = tid & 15;            // column group
    const int ty = tid >> 4;            // row group

    const float* aptr = A  + (size_t)(m0 + lr) * EMB + lc;
    const float* bptr = Wt + (size_t)(n0 + lr) * EMB + lc;

    float acc[8][8];
#pragma unroll
    for (int i = 0; i < 8; i++)
#pragma unroll
        for (int j = 0; j < 8; j++) acc[i][j] = 0.0f;

    for (int k0 = 0; k0 < EMB; k0 += 8) {
        float4 av = *(const float4*)(aptr + k0);
        float4 bv = *(const float4*)(bptr + k0);
        As[lc + 0][lr] = av.x; As[lc + 1][lr] = av.y;
        As[lc + 2][lr] = av.z; As[lc + 3][lr] = av.w;
        Bs[lc + 0][lr] = bv.x; Bs[lc + 1][lr] = bv.y;
        Bs[lc + 2][lr] = bv.z; Bs[lc + 3][lr] = bv.w;
        __syncthreads();
#pragma unroll
        for (int kk = 0; kk < 8; kk++) {
            float a[8], b[8];
            *(float4*)&a[0] = *(const float4*)&As[kk][ty * 8];
            *(float4*)&a[4] = *(const float4*)&As[kk][ty * 8 + 4];
            *(float4*)&b[0] = *(const float4*)&Bs[kk][tx * 8];
            *(float4*)&b[4] = *(const float4*)&Bs[kk][tx * 8 + 4];
#pragma unroll
            for (int i = 0; i < 8; i++)
#pragma unroll
                for (int j = 0; j < 8; j++)
                    acc[i][j] = fmaf(a[i], b[j], acc[i][j]);
        }
        __syncthreads();
    }

    float bvv[8];
    *(float4*)&bvv[0] = *(const float4*)(bias + n0 + tx * 8);
    *(float4*)&bvv[4] = *(const float4*)(bias + n0 + tx * 8 + 4);
#pragma unroll
    for (int i = 0; i < 8; i++) {
        float* cp = g_C + (size_t)(m0 + ty * 8 + i) * O3 + n0 + tx * 8;
        float4 w0 = make_float4(acc[i][0] + bvv[0], acc[i][1] + bvv[1],
                                acc[i][2] + bvv[2], acc[i][3] + bvv[3]);
        float4 w1 = make_float4(acc[i][4] + bvv[4], acc[i][5] + bvv[5],
                                acc[i][6] + bvv[6], acc[i][7] + bvv[7]);
        *(float4*)cp       = w0;
        *(float4*)(cp + 4) = w1;
    }
}

// ---------------------------------------------------------------------------
// K2: per head-batch B: E = exp(0.125 * Q @ K^T), accumulate row sums into g_Z.
// Q[B][l][d] = g_C[(l*8+b)*1536 + h*192 + d]   (bias already folded in)
// K[B][m][d] = g_C[(m*8+b)*1536 + h*192 + 64 + d]
// 128x128 tile over (queries m0, keys n0), K=64 in chunks of 16.
// ---------------------------------------------------------------------------
__global__ void __launch_bounds__(256) k2_scores()
{
    __shared__ float Qs[16][128];
    __shared__ float Ks[16][128];
    const int tid = threadIdx.x;
    const int B  = blockIdx.z;
    const int bb = B >> 3, hh = B & 7;
    const int n0 = blockIdx.x * 128;    // keys
    const int m0 = blockIdx.y * 128;    // queries
    const int tx = tid & 15, ty = tid >> 4;
    const int lr = tid >> 1;
    const int lc = (tid & 1) << 3;      // 0 or 8

    const float* qbase = g_C + (size_t)bb * O3 + hh * 192;
    const float* kbase = qbase + 64;
    const size_t ROWSTRIDE = (size_t)BATCH_BS * O3;   // 12288

    float acc[8][8];
#pragma unroll
    for (int i = 0; i < 8; i++)
#pragma unroll
        for (int j = 0; j < 8; j++) acc[i][j] = 0.0f;

    for (int k0 = 0; k0 < 64; k0 += 16) {
        const float* qp = qbase + (size_t)(m0 + lr) * ROWSTRIDE + k0 + lc;
        const float* kp = kbase + (size_t)(n0 + lr) * ROWSTRIDE + k0 + lc;
        float4 q0 = *(const float4*)qp;
        float4 q1 = *(const float4*)(qp + 4);
        float4 p0 = *(const float4*)kp;
        float4 p1 = *(const float4*)(kp + 4);
        Qs[lc + 0][lr] = q0.x; Qs[lc + 1][lr] = q0.y;
        Qs[lc + 2][lr] = q0.z; Qs[lc + 3][lr] = q0.w;
        Qs[lc + 4][lr] = q1.x; Qs[lc + 5][lr] = q1.y;
        Qs[lc + 6][lr] = q1.z; Qs[lc + 7][lr] = q1.w;
        Ks[lc + 0][lr] = p0.x; Ks[lc + 1][lr] = p0.y;
        Ks[lc + 2][lr] = p0.z; Ks[lc + 3][lr] = p0.w;
        Ks[lc + 4][lr] = p1.x; Ks[lc + 5][lr] = p1.y;
        Ks[lc + 6][lr] = p1.z; Ks[lc + 7][lr] = p1.w;
        __syncthreads();
#pragma unroll
        for (int kk = 0; kk < 16; kk++) {
            float a[8], b[8];
            *(float4*)&a[0] = *(const float4*)&Qs[kk][ty * 8];
            *(float4*)&a[4] = *(const float4*)&Qs[kk][ty * 8 + 4];
            *(float4*)&b[0] = *(const float4*)&Ks[kk][tx * 8];
            *(float4*)&b[4] = *(const float4*)&Ks[kk][tx * 8 + 4];
#pragma unroll
            for (int i = 0; i < 8; i++)
#pragma unroll
                for (int j = 0; j < 8; j++)
                    acc[i][j] = fmaf(a[i], b[j], acc[i][j]);
        }
        __syncthreads();
    }

    // Epilogue: exp, store E, reduce row partial sums, atomic-add into g_Z.
    const size_t ebase = ((size_t)B << 20) + (size_t)m0 * 1024 + n0 + tx * 8;
#pragma unroll
    for (int i = 0; i < 8; i++) {
        float e[8];
        float rp = 0.0f;
#pragma unroll
        for (int j = 0; j < 8; j++) {
            e[j] = __expf(acc[i][j] * 0.125f);
            rp += e[j];
        }
        float* ep = g_E + ebase + (size_t)(ty * 8 + i) * 1024;
        *(float4*)ep       = make_float4(e[0], e[1], e[2], e[3]);
        *(float4*)(ep + 4) = make_float4(e[4], e[5], e[6], e[7]);
        // reduce across tx (16 threads per row live in one half-warp)
        rp += __shfl_down_sync(0xffffffffu, rp, 8, 16);
        rp += __shfl_down_sync(0xffffffffu, rp, 4, 16);
        rp += __shfl_down_sync(0xffffffffu, rp, 2, 16);
        rp += __shfl_down_sync(0xffffffffu, rp, 1, 16);
        if (tx == 0)
            atomicAdd(&g_Z[B * 1024 + m0 + ty * 8 + i], rp);
    }
}

// ---------------------------------------------------------------------------
// K2b: Z -> 1/Z
// ---------------------------------------------------------------------------
__global__ void k_zrecip() {
    const int i = blockIdx.x * 1024 + threadIdx.x;
    g_Z[i] = 1.0f / g_Z[i];
}

// ---------------------------------------------------------------------------
// K3: attn_weights[B][m] = sum_l E[B][l][m] * (1/Z[B][l])
// CTA = (B, 128-column tile); 256 threads = 128 cols x 2 row-groups.
// ---------------------------------------------------------------------------
__global__ void __launch_bounds__(256) k3_colsum()
{
    const int B  = blockIdx.y;
    const int m0 = blockIdx.x * 128;
    const int tid = threadIdx.x;
    const int col = tid & 127, rg = tid >> 7;
    const float* ep = g_E + ((size_t)B << 20) + m0 + col;
    const float* zp = g_Z + B * 1024;
    float acc = 0.0f;
#pragma unroll 4
    for (int l = rg; l < 1024; l += 2)
        acc = fmaf(ep[(size_t)l * 1024], zp[l], acc);
    __shared__ float sh[256];
    sh[tid] = acc;
    __syncthreads();
    if (rg == 0)
        g_W[B * 1024 + m0 + col] = sh[col] + sh[col + 128];
}

// ---------------------------------------------------------------------------
// K4: out_v[B][d] = sum_m W[B][m] * V[B][m][d]; GroupNorm over d=64 per B.
// One CTA per B, 512 threads = 8 m-groups x 64 d.
// ---------------------------------------------------------------------------
__global__ void __launch_bounds__(512) k4_out(
    const float* __restrict__ gw, const float* __restrict__ gb,
    float* __restrict__ out)
{
    const int B  = blockIdx.x;
    const int bb = B >> 3, hh = B & 7;
    const int tid = threadIdx.x;
    const int d = tid & 63, mg = tid >> 6;    // mg in 0..7
    const float* vptr = g_C + (size_t)bb * O3 + hh * 192 + 128 + d;
    const float* wp = g_W + B * 1024;
    const size_t ROWSTRIDE = (size_t)BATCH_BS * O3;   // 12288

    float acc = 0.0f;
#pragma unroll 4
    for (int m = mg; m < 1024; m += 8)
        acc = fmaf(wp[m], vptr[(size_t)m * ROWSTRIDE], acc);

    __shared__ float part[8][64];
    __shared__ float vout[64];
    __shared__ float s_mean, s_rstd;
    part[mg][d] = acc;
    __syncthreads();

    if (tid < 64) {
        float s = 0.0f;
#pragma unroll
        for (int g = 0; g < 8; g++) s += part[g][tid];
        vout[tid] = s;
    }
    __syncthreads();

    if (tid < 32) {
        float x1 = vout[tid], x2 = vout[tid + 32];
        float s  = x1 + x2;
        float sq = x1 * x1 + x2 * x2;
#pragma unroll
        for (int o = 16; o > 0; o >>= 1) {
            s  += __shfl_down_sync(0xffffffffu, s, o);
            sq += __shfl_down_sync(0xffffffffu, sq, o);
        }
        if (tid == 0) {
            float mean = s * (1.0f / 64.0f);
            float var  = sq * (1.0f / 64.0f) - mean * mean;
            s_mean = mean;
            s_rstd = rsqrtf(var + 1e-5f);
        }
    }
    __syncthreads();

    if (tid < 64)
        out[bb * 512 + hh * 64 + tid] =
            (vout[tid] - s_mean) * s_rstd * gw[hh] + gb[hh];
}

// ---------------------------------------------------------------------------
// Launcher (graph-capturable: kernel launches only, default stream)
// ---------------------------------------------------------------------------
extern "C" void kernel_launch(void* const* d_in, const int* in_sizes, int n_in,
                              void* d_out, int out_size)
{
    (void)in_sizes; (void)n_in; (void)out_size;
    const float* emb = (const float*)d_in[0];   // [1024, 8, 512]
    const float* Wq  = (const float*)d_in[1];   // [1536, 512]
    const float* bq  = (const float*)d_in[2];   // [1536]
    const float* gw  = (const float*)d_in[3];   // [8]
    const float* gb  = (const float*)d_in[4];   // [8]
    float* out = (float*)d_out;                 // [8, 512]

    k_zzero  <<<64, 1024>>>();
    k1_qkv_gemm<<<dim3(12, 64), 256>>>(emb, Wq, bq);
    k2_scores<<<dim3(8, 8, 64), 256>>>();
    k_zrecip <<<64, 1024>>>();
    k3_colsum<<<dim3(8, 64), 256>>>();
    k4_out   <<<64, 512>>>(gw, gb, out);
}

// round 2
// speedup vs baseline: 1.8241x; 1.8241x over previous
#include <cuda_runtime.h>
#include <cstdint>

// Problem constants
#define L_SEQ 1024
#define BATCH_BS 8
#define EMB 512
#define NH 8
#define DH 64
#define O3 1536          // 3*NH*DH
#define MROWS 8192       // L_SEQ * BATCH_BS
#define NB 64            // BATCH_BS * NH

// Scratch (device globals — no allocation allowed)
__device__ float g_C[(size_t)MROWS * O3];              // qkv projection output (+bias)
__device__ float g_E[(size_t)NB * L_SEQ * L_SEQ];      // exp(scores)
__device__ float g_Z[NB * L_SEQ];                      // row sums -> reciprocals
__device__ float g_W[NB * L_SEQ];                      // attn_weights (column sums)

// ---------------------------------------------------------------------------
// tf32 helpers
// ---------------------------------------------------------------------------
__device__ __forceinline__ uint32_t f2tf32(float x) {
    uint32_t u;
    asm("cvt.rna.tf32.f32 %0, %1;" : "=r"(u) : "f"(x));
    return u;
}

__device__ __forceinline__ void mma_tf32(float* d, const uint32_t* a, const uint32_t* b) {
    asm volatile(
        "mma.sync.aligned.m16n8k8.row.col.f32.tf32.tf32.f32 "
        "{%0,%1,%2,%3}, {%4,%5,%6,%7}, {%8,%9}, {%0,%1,%2,%3};\n"
        : "+f"(d[0]), "+f"(d[1]), "+f"(d[2]), "+f"(d[3])
        : "r"(a[0]), "r"(a[1]), "r"(a[2]), "r"(a[3]), "r"(b[0]), "r"(b[1]));
}

// ---------------------------------------------------------------------------
// K0: zero Z (K2 accumulates with atomics; must reset every graph replay)
// ---------------------------------------------------------------------------
__global__ void k_zzero() {
    g_Z[blockIdx.x * 1024 + threadIdx.x] = 0.0f;
}

// ---------------------------------------------------------------------------
// K1: C[8192,1536] = emb[8192,512] @ W_qkv[1536,512]^T + bias  (tf32 mma, NT)
// CTA tile 128x128, BK=32, 256 threads = 8 warps (2m x 4n), warp tile 64x32.
// ---------------------------------------------------------------------------
__global__ void __launch_bounds__(256) k1_qkv_gemm(
    const float* __restrict__ A, const float* __restrict__ Wt,
    const float* __restrict__ bias)
{
    __shared__ uint32_t As[32][136];   // [k][m], pad stride%32==8 -> conflict free
    __shared__ uint32_t Bs[32][136];   // [k][n]

    const int tid  = threadIdx.x;
    const int warp = tid >> 5;
    const int lane = tid & 31;
    const int g = lane >> 2, t = lane & 3;
    const int wm0 = (warp >> 2) * 64;      // 0 or 64
    const int wn0 = (warp & 3) * 32;       // 0..96
    const int m0 = blockIdx.y * 128;
    const int n0 = blockIdx.x * 128;

    const int lrow = tid >> 1;             // 0..127
    const int lk   = (tid & 1) * 16;       // 0 or 16
    const float* aptr = A  + (size_t)(m0 + lrow) * EMB + lk;
    const float* bptr = Wt + (size_t)(n0 + lrow) * EMB + lk;

    float acc[4][4][4];
#pragma unroll
    for (int i = 0; i < 4; i++)
#pragma unroll
        for (int j = 0; j < 4; j++)
#pragma unroll
            for (int c = 0; c < 4; c++) acc[i][j][c] = 0.0f;

    for (int k0 = 0; k0 < EMB; k0 += 32) {
        float4 av[4], bv[4];
#pragma unroll
        for (int j = 0; j < 4; j++) {
            av[j] = *(const float4*)(aptr + k0 + 4 * j);
            bv[j] = *(const float4*)(bptr + k0 + 4 * j);
        }
        __syncthreads();   // previous stage fully consumed
#pragma unroll
        for (int j = 0; j < 4; j++) {
            As[lk + 4*j + 0][lrow] = f2tf32(av[j].x);
            As[lk + 4*j + 1][lrow] = f2tf32(av[j].y);
            As[lk + 4*j + 2][lrow] = f2tf32(av[j].z);
            As[lk + 4*j + 3][lrow] = f2tf32(av[j].w);
            Bs[lk + 4*j + 0][lrow] = f2tf32(bv[j].x);
            Bs[lk + 4*j + 1][lrow] = f2tf32(bv[j].y);
            Bs[lk + 4*j + 2][lrow] = f2tf32(bv[j].z);
            Bs[lk + 4*j + 3][lrow] = f2tf32(bv[j].w);
        }
        __syncthreads();
#pragma unroll
        for (int kk = 0; kk < 32; kk += 8) {
            uint32_t af[4][4], bf[4][2];
#pragma unroll
            for (int im = 0; im < 4; im++) {
                const int m = wm0 + im * 16 + g;
                af[im][0] = As[kk + t    ][m];
                af[im][1] = As[kk + t    ][m + 8];
                af[im][2] = As[kk + t + 4][m];
                af[im][3] = As[kk + t + 4][m + 8];
            }
#pragma unroll
            for (int in = 0; in < 4; in++) {
                const int n = wn0 + in * 8 + g;
                bf[in][0] = Bs[kk + t    ][n];
                bf[in][1] = Bs[kk + t + 4][n];
            }
#pragma unroll
            for (int im = 0; im < 4; im++)
#pragma unroll
                for (int in = 0; in < 4; in++)
                    mma_tf32(acc[im][in], af[im], bf[in]);
        }
    }

    // epilogue: + bias, store fp32
#pragma unroll
    for (int im = 0; im < 4; im++) {
        const int r0 = m0 + wm0 + im * 16 + g;
#pragma unroll
        for (int in = 0; in < 4; in++) {
            const int col = n0 + wn0 + in * 8 + 2 * t;
            const float b0 = bias[col], b1 = bias[col + 1];
            float* p0 = g_C + (size_t)r0 * O3 + col;
            float* p1 = g_C + (size_t)(r0 + 8) * O3 + col;
            *(float2*)p0 = make_float2(acc[im][in][0] + b0, acc[im][in][1] + b1);
            *(float2*)p1 = make_float2(acc[im][in][2] + b0, acc[im][in][3] + b1);
        }
    }
}

// ---------------------------------------------------------------------------
// K2: per head-batch B: E = exp(0.125 * Q @ K^T), row sums into g_Z (atomics).
// Q[B][l][d] = g_C[(l*8+b)*1536 + h*192 + d], K at +64. tf32 mma, tile 128x128.
// ---------------------------------------------------------------------------
__global__ void __launch_bounds__(256) k2_scores()
{
    __shared__ uint32_t Qs[32][136];   // [k][m]
    __shared__ uint32_t Ks[32][136];   // [k][n]

    const int tid  = threadIdx.x;
    const int warp = tid >> 5;
    const int lane = tid & 31;
    const int g = lane >> 2, t = lane & 3;
    const int wm0 = (warp >> 2) * 64;
    const int wn0 = (warp & 3) * 32;

    const int B  = blockIdx.z;
    const int bb = B >> 3, hh = B & 7;
    const int n0 = blockIdx.x * 128;    // keys
    const int m0 = blockIdx.y * 128;    // queries

    const float* qbase = g_C + (size_t)bb * O3 + hh * 192;
    const float* kbase = qbase + 64;
    const size_t RS = (size_t)BATCH_BS * O3;   // 12288

    const int lrow = tid >> 1;
    const int lk   = (tid & 1) * 16;

    float acc[4][4][4];
#pragma unroll
    for (int i = 0; i < 4; i++)
#pragma unroll
        for (int j = 0; j < 4; j++)
#pragma unroll
            for (int c = 0; c < 4; c++) acc[i][j][c] = 0.0f;

    for (int ks = 0; ks < 64; ks += 32) {
        const float* qp = qbase + (size_t)(m0 + lrow) * RS + ks + lk;
        const float* kp = kbase + (size_t)(n0 + lrow) * RS + ks + lk;
        float4 qv[4], kv[4];
#pragma unroll
        for (int j = 0; j < 4; j++) {
            qv[j] = *(const float4*)(qp + 4 * j);
            kv[j] = *(const float4*)(kp + 4 * j);
        }
        __syncthreads();
#pragma unroll
        for (int j = 0; j < 4; j++) {
            Qs[lk + 4*j + 0][lrow] = f2tf32(qv[j].x);
            Qs[lk + 4*j + 1][lrow] = f2tf32(qv[j].y);
            Qs[lk + 4*j + 2][lrow] = f2tf32(qv[j].z);
            Qs[lk + 4*j + 3][lrow] = f2tf32(qv[j].w);
            Ks[lk + 4*j + 0][lrow] = f2tf32(kv[j].x);
            Ks[lk + 4*j + 1][lrow] = f2tf32(kv[j].y);
            Ks[lk + 4*j + 2][lrow] = f2tf32(kv[j].z);
            Ks[lk + 4*j + 3][lrow] = f2tf32(kv[j].w);
        }
        __syncthreads();
#pragma unroll
        for (int kk = 0; kk < 32; kk += 8) {
            uint32_t af[4][4], bf[4][2];
#pragma unroll
            for (int im = 0; im < 4; im++) {
                const int m = wm0 + im * 16 + g;
                af[im][0] = Qs[kk + t    ][m];
                af[im][1] = Qs[kk + t    ][m + 8];
                af[im][2] = Qs[kk + t + 4][m];
                af[im][3] = Qs[kk + t + 4][m + 8];
            }
#pragma unroll
            for (int in = 0; in < 4; in++) {
                const int n = wn0 + in * 8 + g;
                bf[in][0] = Ks[kk + t    ][n];
                bf[in][1] = Ks[kk + t + 4][n];
            }
#pragma unroll
            for (int im = 0; im < 4; im++)
#pragma unroll
                for (int in = 0; in < 4; in++)
                    mma_tf32(acc[im][in], af[im], bf[in]);
        }
    }

    // Epilogue: exp, store E, row-sum reduce over t, atomicAdd into g_Z.
    const size_t ebase = ((size_t)B << 20);
#pragma unroll
    for (int im = 0; im < 4; im++) {
#pragma unroll
        for (int half = 0; half < 2; half++) {
            const int row = m0 + wm0 + im * 16 + g + half * 8;
            float rp = 0.0f;
#pragma unroll
            for (int in = 0; in < 4; in++) {
                const float e0 = __expf(acc[im][in][2 * half    ] * 0.125f);
                const float e1 = __expf(acc[im][in][2 * half + 1] * 0.125f);
                rp += e0 + e1;
                float* ep = g_E + ebase + (size_t)row * 1024 + n0 + wn0 + in * 8 + 2 * t;
                *(float2*)ep = make_float2(e0, e1);
            }
            rp += __shfl_xor_sync(0xffffffffu, rp, 1);
            rp += __shfl_xor_sync(0xffffffffu, rp, 2);
            if (t == 0)
                atomicAdd(&g_Z[B * 1024 + row], rp);
        }
    }
}

// ---------------------------------------------------------------------------
// K2b: Z -> 1/Z
// ---------------------------------------------------------------------------
__global__ void k_zrecip() {
    const int i = blockIdx.x * 1024 + threadIdx.x;
    g_Z[i] = 1.0f / g_Z[i];
}

// ---------------------------------------------------------------------------
// K3: attn_weights[B][m] = sum_l E[B][l][m] * (1/Z[B][l])
// ---------------------------------------------------------------------------
__global__ void __launch_bounds__(256) k3_colsum()
{
    const int B  = blockIdx.y;
    const int m0 = blockIdx.x * 128;
    const int tid = threadIdx.x;
    const int col = tid & 127, rg = tid >> 7;
    const float* ep = g_E + ((size_t)B << 20) + m0 + col;
    const float* zp = g_Z + B * 1024;
    float acc = 0.0f;
#pragma unroll 4
    for (int l = rg; l < 1024; l += 2)
        acc = fmaf(ep[(size_t)l * 1024], zp[l], acc);
    __shared__ float sh[256];
    sh[tid] = acc;
    __syncthreads();
    if (rg == 0)
        g_W[B * 1024 + m0 + col] = sh[col] + sh[col + 128];
}

// ---------------------------------------------------------------------------
// K4: out_v[B][d] = sum_m W[B][m] * V[B][m][d]; GroupNorm over d=64 per B.
// ---------------------------------------------------------------------------
__global__ void __launch_bounds__(512) k4_out(
    const float* __restrict__ gw, const float* __restrict__ gb,
    float* __restrict__ out)
{
    const int B  = blockIdx.x;
    const int bb = B >> 3, hh = B & 7;
    const int tid = threadIdx.x;
    const int d = tid & 63, mg = tid >> 6;
    const float* vptr = g_C + (size_t)bb * O3 + hh * 192 + 128 + d;
    const float* wp = g_W + B * 1024;
    const size_t RS = (size_t)BATCH_BS * O3;

    float acc = 0.0f;
#pragma unroll 4
    for (int m = mg; m < 1024; m += 8)
        acc = fmaf(wp[m], vptr[(size_t)m * RS], acc);

    __shared__ float part[8][64];
    __shared__ float vout[64];
    __shared__ float s_mean, s_rstd;
    part[mg][d] = acc;
    __syncthreads();

    if (tid < 64) {
        float s = 0.0f;
#pragma unroll
        for (int g = 0; g < 8; g++) s += part[g][tid];
        vout[tid] = s;
    }
    __syncthreads();

    if (tid < 32) {
        float x1 = vout[tid], x2 = vout[tid + 32];
        float s  = x1 + x2;
        float sq = x1 * x1 + x2 * x2;
#pragma unroll
        for (int o = 16; o > 0; o >>= 1) {
            s  += __shfl_down_sync(0xffffffffu, s, o);
            sq += __shfl_down_sync(0xffffffffu, sq, o);
        }
        if (tid == 0) {
            float mean = s * (1.0f / 64.0f);
            float var  = sq * (1.0f / 64.0f) - mean * mean;
            s_mean = mean;
            s_rstd = rsqrtf(var + 1e-5f);
        }
    }
    __syncthreads();

    if (tid < 64)
        out[bb * 512 + hh * 64 + tid] =
            (vout[tid] - s_mean) * s_rstd * gw[hh] + gb[hh];
}

// ---------------------------------------------------------------------------
// Launcher (graph-capturable: kernel launches only, default stream)
// ---------------------------------------------------------------------------
extern "C" void kernel_launch(void* const* d_in, const int* in_sizes, int n_in,
                              void* d_out, int out_size)
{
    (void)in_sizes; (void)n_in; (void)out_size;
    const float* emb = (const float*)d_in[0];   // [1024, 8, 512]
    const float* Wq  = (const float*)d_in[1];   // [1536, 512]
    const float* bq  = (const float*)d_in[2];   // [1536]
    const float* gw  = (const float*)d_in[3];   // [8]
    const float* gb  = (const float*)d_in[4];   // [8]
    float* out = (float*)d_out;                 // [8, 512]

    k_zzero  <<<64, 1024>>>();
    k1_qkv_gemm<<<dim3(12, 64), 256>>>(emb, Wq, bq);
    k2_scores<<<dim3(8, 8, 64), 256>>>();
    k_zrecip <<<64, 1024>>>();
    k3_colsum<<<dim3(8, 64), 256>>>();
    k4_out   <<<64, 512>>>(gw, gb, out);
}

// round 3
// speedup vs baseline: 3.3590x; 1.8415x over previous
#include <cuda_runtime.h>
#include <cuda_fp16.h>
#include <cstdint>

#define L_SEQ 1024
#define BATCH_BS 8
#define EMB 512
#define O3 1536
#define NB 64            // BATCH_BS * NH

// Scratch (device globals)
__device__ __half g_Q[(size_t)NB * L_SEQ * 64];   // 8 MB
__device__ __half g_K[(size_t)NB * L_SEQ * 64];   // 8 MB
__device__ float  g_V[(size_t)NB * L_SEQ * 64];   // 16 MB
__device__ float  g_Z[NB * L_SEQ];                // row sums -> reciprocals
__device__ float  g_W[NB * L_SEQ];                // attn weights (col sums)

// ---------------------------------------------------------------------------
// helpers
// ---------------------------------------------------------------------------
__device__ __forceinline__ uint32_t f22h2(float lo, float hi) {
    __half2 h = __floats2half2_rn(lo, hi);
    return reinterpret_cast<uint32_t&>(h);
}

__device__ __forceinline__ void ldsm4(uint32_t& r0, uint32_t& r1,
                                      uint32_t& r2, uint32_t& r3,
                                      const __half* p) {
    uint32_t addr = (uint32_t)__cvta_generic_to_shared(p);
    asm volatile("ldmatrix.sync.aligned.m8n8.x4.shared.b16 {%0,%1,%2,%3}, [%4];"
                 : "=r"(r0), "=r"(r1), "=r"(r2), "=r"(r3) : "r"(addr));
}

__device__ __forceinline__ void mma_f16(float* d, const uint32_t* a, const uint32_t* b) {
    asm volatile(
        "mma.sync.aligned.m16n8k16.row.col.f32.f16.f16.f32 "
        "{%0,%1,%2,%3}, {%4,%5,%6,%7}, {%8,%9}, {%0,%1,%2,%3};\n"
        : "+f"(d[0]), "+f"(d[1]), "+f"(d[2]), "+f"(d[3])
        : "r"(a[0]), "r"(a[1]), "r"(a[2]), "r"(a[3]), "r"(b[0]), "r"(b[1]));
}

// ---------------------------------------------------------------------------
// K0: zero Z and W (both accumulated via atomics each replay)
// ---------------------------------------------------------------------------
__global__ void k_zero() {
    const int i = blockIdx.x * 1024 + threadIdx.x;
    g_Z[i] = 0.0f;
    g_W[i] = 0.0f;
}

// ---------------------------------------------------------------------------
// K1: QKV projection, fp16 mma, NT. C = emb[8192,512] @ W[1536,512]^T + bias.
// Epilogue scatters into g_Q/g_K (fp16) and g_V (fp32) in [B][l][d] layout.
// CTA 128x128, BK=32, 8 warps (2m x 4n), warp tile 64x32.
// ---------------------------------------------------------------------------
#define SA 40   // padded row stride (halves): 20 words -> conflict-free ldmatrix
__global__ void __launch_bounds__(256) k1_qkv(
    const float* __restrict__ A, const float* __restrict__ Wt,
    const float* __restrict__ bias)
{
    __shared__ __half As[128 * SA];
    __shared__ __half Bs[128 * SA];

    const int tid  = threadIdx.x;
    const int warp = tid >> 5;
    const int lane = tid & 31;
    const int g = lane >> 2, t = lane & 3;
    const int wm0 = (warp >> 2) * 64;
    const int wn0 = (warp & 3) * 32;
    const int m0 = blockIdx.y * 128;
    const int n0 = blockIdx.x * 128;

    const int lrow = tid >> 1;
    const int lk   = (tid & 1) * 16;
    const float* ap = A  + (size_t)(m0 + lrow) * EMB + lk;
    const float* bp = Wt + (size_t)(n0 + lrow) * EMB + lk;

    const int lm = lane & 15;           // ldmatrix row select
    const int lc = (lane >> 4) * 8;     // ldmatrix k-chunk select

    float acc[4][4][4];
#pragma unroll
    for (int i = 0; i < 4; i++)
#pragma unroll
        for (int j = 0; j < 4; j++)
#pragma unroll
            for (int c = 0; c < 4; c++) acc[i][j][c] = 0.0f;

    for (int k0 = 0; k0 < EMB; k0 += 32) {
        float4 av[4], bv[4];
#pragma unroll
        for (int j = 0; j < 4; j++) {
            av[j] = *(const float4*)(ap + k0 + 4 * j);
            bv[j] = *(const float4*)(bp + k0 + 4 * j);
        }
        __syncthreads();
        uint4 ua0 = make_uint4(f22h2(av[0].x, av[0].y), f22h2(av[0].z, av[0].w),
                               f22h2(av[1].x, av[1].y), f22h2(av[1].z, av[1].w));
        uint4 ua1 = make_uint4(f22h2(av[2].x, av[2].y), f22h2(av[2].z, av[2].w),
                               f22h2(av[3].x, av[3].y), f22h2(av[3].z, av[3].w));
        uint4 ub0 = make_uint4(f22h2(bv[0].x, bv[0].y), f22h2(bv[0].z, bv[0].w),
                               f22h2(bv[1].x, bv[1].y), f22h2(bv[1].z, bv[1].w));
        uint4 ub1 = make_uint4(f22h2(bv[2].x, bv[2].y), f22h2(bv[2].z, bv[2].w),
                               f22h2(bv[3].x, bv[3].y), f22h2(bv[3].z, bv[3].w));
        *(uint4*)(As + lrow * SA + lk)     = ua0;
        *(uint4*)(As + lrow * SA + lk + 8) = ua1;
        *(uint4*)(Bs + lrow * SA + lk)     = ub0;
        *(uint4*)(Bs + lrow * SA + lk + 8) = ub1;
        __syncthreads();

#pragma unroll
        for (int kk = 0; kk < 32; kk += 16) {
            uint32_t af[4][4];
#pragma unroll
            for (int im = 0; im < 4; im++)
                ldsm4(af[im][0], af[im][1], af[im][2], af[im][3],
                      As + (wm0 + im * 16 + lm) * SA + kk + lc);
            uint32_t br0[4], br1[4];
            ldsm4(br0[0], br0[1], br0[2], br0[3], Bs + (wn0 +      lm) * SA + kk + lc);
            ldsm4(br1[0], br1[1], br1[2], br1[3], Bs + (wn0 + 16 + lm) * SA + kk + lc);
            uint32_t bf[4][2] = {{br0[0], br0[2]}, {br0[1], br0[3]},
                                 {br1[0], br1[2]}, {br1[1], br1[3]}};
#pragma unroll
            for (int im = 0; im < 4; im++)
#pragma unroll
                for (int in = 0; in < 4; in++)
                    mma_f16(acc[im][in], af[im], bf[in]);
        }
    }

    // Epilogue: +bias, scatter to g_Q / g_K (half) and g_V (float), [B][l][d].
#pragma unroll
    for (int im = 0; im < 4; im++) {
        const int r0 = m0 + wm0 + im * 16 + g;
#pragma unroll
        for (int in = 0; in < 4; in++) {
            const int c   = n0 + wn0 + in * 8 + 2 * t;
            const int h   = c / 192;
            const int rem = c - h * 192;
            const int sect = rem >> 6;
            const int d    = rem & 63;
            const float b0 = __ldg(bias + c), b1 = __ldg(bias + c + 1);
#pragma unroll
            for (int hf = 0; hf < 2; hf++) {
                const int r = r0 + hf * 8;
                const int l = r >> 3, bb = r & 7;
                const size_t off = ((size_t)(bb * 8 + h) << 16) + l * 64 + d;
                const float v0 = acc[im][in][2 * hf    ] + b0;
                const float v1 = acc[im][in][2 * hf + 1] + b1;
                if (sect == 0) {
                    *(uint32_t*)(g_Q + off) = f22h2(v0, v1);
                } else if (sect == 1) {
                    *(uint32_t*)(g_K + off) = f22h2(v0, v1);
                } else {
                    *(float2*)(g_V + off) = make_float2(v0, v1);
                }
            }
        }
    }
}

// ---------------------------------------------------------------------------
// K2: scores S = Q @ K^T per B, tile 128x128, d=64 fully in SMEM (no k-loop).
// PASS2=false: Z[row] += sum over cols of exp(0.125*S)        (row sums)
// PASS2=true : W[col] += sum over rows of exp(0.125*S)/Z[row] (col sums)
// ---------------------------------------------------------------------------
#define SQ 72   // padded row stride (halves): 36 words -> conflict-free ldmatrix
template<bool PASS2>
__global__ void __launch_bounds__(256) k2_attn()
{
    __shared__ __half Qs[128 * SQ];
    __shared__ __half Ks[128 * SQ];

    const int tid  = threadIdx.x;
    const int warp = tid >> 5;
    const int lane = tid & 31;
    const int g = lane >> 2, t = lane & 3;
    const int wm0 = (warp >> 2) * 64;
    const int wn0 = (warp & 3) * 32;

    const int B  = blockIdx.z;
    const int n0 = blockIdx.x * 128;    // keys   (output index m')
    const int m0 = blockIdx.y * 128;    // queries (softmax row l)

    const __half* qg = g_Q + ((size_t)B << 16) + (size_t)m0 * 64;
    const __half* kg = g_K + ((size_t)B << 16) + (size_t)n0 * 64;

#pragma unroll
    for (int j = 0; j < 4; j++) {
        const int idx = tid + j * 256;
        const int row = idx >> 3;
        const int ch  = (idx & 7) * 8;
        *(uint4*)(Qs + row * SQ + ch) = *(const uint4*)(qg + row * 64 + ch);
        *(uint4*)(Ks + row * SQ + ch) = *(const uint4*)(kg + row * 64 + ch);
    }
    __syncthreads();

    const int lm = lane & 15;
    const int lc = (lane >> 4) * 8;

    float acc[4][4][4];
#pragma unroll
    for (int i = 0; i < 4; i++)
#pragma unroll
        for (int j = 0; j < 4; j++)
#pragma unroll
            for (int c = 0; c < 4; c++) acc[i][j][c] = 0.0f;

#pragma unroll
    for (int kk = 0; kk < 64; kk += 16) {
        uint32_t af[4][4];
#pragma unroll
        for (int im = 0; im < 4; im++)
            ldsm4(af[im][0], af[im][1], af[im][2], af[im][3],
                  Qs + (wm0 + im * 16 + lm) * SQ + kk + lc);
        uint32_t br0[4], br1[4];
        ldsm4(br0[0], br0[1], br0[2], br0[3], Ks + (wn0 +      lm) * SQ + kk + lc);
        ldsm4(br1[0], br1[1], br1[2], br1[3], Ks + (wn0 + 16 + lm) * SQ + kk + lc);
        uint32_t bf[4][2] = {{br0[0], br0[2]}, {br0[1], br0[3]},
                             {br1[0], br1[2]}, {br1[1], br1[3]}};
#pragma unroll
        for (int im = 0; im < 4; im++)
#pragma unroll
            for (int in = 0; in < 4; in++)
                mma_f16(acc[im][in], af[im], bf[in]);
    }

    if (!PASS2) {
        // row sums -> g_Z
#pragma unroll
        for (int im = 0; im < 4; im++) {
#pragma unroll
            for (int hf = 0; hf < 2; hf++) {
                const int row = m0 + wm0 + im * 16 + g + hf * 8;
                float rp = 0.0f;
#pragma unroll
                for (int in = 0; in < 4; in++)
                    rp += __expf(acc[im][in][2 * hf] * 0.125f)
                        + __expf(acc[im][in][2 * hf + 1] * 0.125f);
                rp += __shfl_xor_sync(0xffffffffu, rp, 1);
                rp += __shfl_xor_sync(0xffffffffu, rp, 2);
                if ((lane & 3) == 0)
                    atomicAdd(&g_Z[B * 1024 + row], rp);
            }
        }
    } else {
        // col sums of exp * (1/Z[row]) -> g_W
        float ca[4][2];
#pragma unroll
        for (int in = 0; in < 4; in++) { ca[in][0] = 0.0f; ca[in][1] = 0.0f; }
#pragma unroll
        for (int im = 0; im < 4; im++) {
            const int rowg = m0 + wm0 + im * 16 + g;
            const float rA = __ldg(&g_Z[B * 1024 + rowg]);
            const float rB = __ldg(&g_Z[B * 1024 + rowg + 8]);
#pragma unroll
            for (int in = 0; in < 4; in++) {
                ca[in][0] += __expf(acc[im][in][0] * 0.125f) * rA
                           + __expf(acc[im][in][2] * 0.125f) * rB;
                ca[in][1] += __expf(acc[im][in][1] * 0.125f) * rA
                           + __expf(acc[im][in][3] * 0.125f) * rB;
            }
        }
#pragma unroll
        for (int in = 0; in < 4; in++) {
#pragma unroll
            for (int s = 0; s < 2; s++) {
                float v = ca[in][s];
                v += __shfl_xor_sync(0xffffffffu, v, 4);
                v += __shfl_xor_sync(0xffffffffu, v, 8);
                v += __shfl_xor_sync(0xffffffffu, v, 16);
                if (lane < 4)
                    atomicAdd(&g_W[B * 1024 + n0 + wn0 + in * 8 + 2 * t + s], v);
            }
        }
    }
}

// ---------------------------------------------------------------------------
// K2b: Z -> 1/Z
// ---------------------------------------------------------------------------
__global__ void k_zrecip() {
    const int i = blockIdx.x * 1024 + threadIdx.x;
    g_Z[i] = 1.0f / g_Z[i];
}

// ---------------------------------------------------------------------------
// K4: out_v[B][d] = sum_m W[B][m] * V[B][m][d]; GroupNorm over d=64 per B.
// ---------------------------------------------------------------------------
__global__ void __launch_bounds__(512) k4_out(
    const float* __restrict__ gw, const float* __restrict__ gb,
    float* __restrict__ out)
{
    const int B  = blockIdx.x;
    const int bb = B >> 3, hh = B & 7;
    const int tid = threadIdx.x;
    const int d = tid & 63, mg = tid >> 6;
    const float* vptr = g_V + ((size_t)B << 16) + d;
    const float* wp = g_W + B * 1024;

    float acc = 0.0f;
#pragma unroll 4
    for (int m = mg; m < 1024; m += 8)
        acc = fmaf(wp[m], vptr[m * 64], acc);

    __shared__ float part[8][64];
    __shared__ float vout[64];
    __shared__ float s_mean, s_rstd;
    part[mg][d] = acc;
    __syncthreads();

    if (tid < 64) {
        float s = 0.0f;
#pragma unroll
        for (int g = 0; g < 8; g++) s += part[g][tid];
        vout[tid] = s;
    }
    __syncthreads();

    if (tid < 32) {
        float x1 = vout[tid], x2 = vout[tid + 32];
        float s  = x1 + x2;
        float sq = x1 * x1 + x2 * x2;
#pragma unroll
        for (int o = 16; o > 0; o >>= 1) {
            s  += __shfl_down_sync(0xffffffffu, s, o);
            sq += __shfl_down_sync(0xffffffffu, sq, o);
        }
        if (tid == 0) {
            float mean = s * (1.0f / 64.0f);
            float var  = sq * (1.0f / 64.0f) - mean * mean;
            s_mean = mean;
            s_rstd = rsqrtf(var + 1e-5f);
        }
    }
    __syncthreads();

    if (tid < 64)
        out[bb * 512 + hh * 64 + tid] =
            (vout[tid] - s_mean) * s_rstd * gw[hh] + gb[hh];
}

// ---------------------------------------------------------------------------
// Launcher (graph-capturable)
// ---------------------------------------------------------------------------
extern "C" void kernel_launch(void* const* d_in, const int* in_sizes, int n_in,
                              void* d_out, int out_size)
{
    (void)in_sizes; (void)n_in; (void)out_size;
    const float* emb = (const float*)d_in[0];
    const float* Wq  = (const float*)d_in[1];
    const float* bq  = (const float*)d_in[2];
    const float* gw  = (const float*)d_in[3];
    const float* gb  = (const float*)d_in[4];
    float* out = (float*)d_out;

    k_zero   <<<64, 1024>>>();
    k1_qkv   <<<dim3(12, 64), 256>>>(emb, Wq, bq);
    k2_attn<false><<<dim3(8, 8, 64), 256>>>();
    k_zrecip <<<64, 1024>>>();
    k2_attn<true> <<<dim3(8, 8, 64), 256>>>();
    k4_out   <<<64, 512>>>(gw, gb, out);
}